// round 13
// baseline (speedup 1.0000x reference)
#include <cuda_runtime.h>
#include <cuda_fp16.h>
#include <cstdint>

#define DQ 256
#define KQ 8192
#define NQ 32768
#define MAXC 128
#define MARGIN 2.5f

typedef unsigned int u32;

// ---------------- device scratch ----------------
__device__ float   g_embedT[KQ * DQ];      // fp32 [K][D]
__device__ __half  g_eh[KQ * DQ];          // fp16 [K][D]
__device__ __half  g_xh[NQ * DQ];          // fp16 [N][D]
__device__ float   g_esq[KQ];
__device__ int     g_cand[(size_t)NQ * MAXC];  // candidate code indices per row
__device__ int     g_ccnt[NQ];                 // candidate counts

// ---------------- helpers ----------------
__device__ __forceinline__ u32 smem_u32(const void* p) {
    u32 a;
    asm("{ .reg .u64 t; cvta.to.shared.u64 t, %1; cvt.u32.u64 %0, t; }" : "=r"(a) : "l"(p));
    return a;
}
__device__ __forceinline__ void cp16(u32 saddr, const void* g) {
    asm volatile("cp.async.cg.shared.global [%0], [%1], 16;" :: "r"(saddr), "l"(g));
}
__device__ __forceinline__ void cp_commit() { asm volatile("cp.async.commit_group;"); }
__device__ __forceinline__ void cp_wait0()  { asm volatile("cp.async.wait_group 0;" ::: "memory"); }

#define LDSM_X4(r, addr) \
    asm volatile("ldmatrix.sync.aligned.m8n8.x4.shared.b16 {%0,%1,%2,%3}, [%4];" \
                 : "=r"((r)[0]), "=r"((r)[1]), "=r"((r)[2]), "=r"((r)[3]) : "r"(addr))

// fp16-accumulate HMMA: C/D are 2 regs (half2 x2)
#define MMAF16(c, a, b0, b1) \
    asm volatile("mma.sync.aligned.m16n8k16.row.col.f16.f16.f16.f16 " \
                 "{%0,%1}, {%2,%3,%4,%5}, {%6,%7}, {%0,%1};" \
                 : "+r"((c)[0]), "+r"((c)[1]) \
                 : "r"((a)[0]), "r"((a)[1]), "r"((a)[2]), "r"((a)[3]), "r"(b0), "r"(b1))

// order-preserving float <-> u32 key (for atomicMin)
__device__ __forceinline__ u32 fkey(float f) {
    u32 b = __float_as_uint(f);
    return (b & 0x80000000u) ? ~b : (b | 0x80000000u);
}
__device__ __forceinline__ float funkey(u32 k) {
    u32 b = (k & 0x80000000u) ? (k & 0x7FFFFFFFu) : ~k;
    return __uint_as_float(b);
}
__device__ __forceinline__ float quadmin(float v) {
    v = fminf(v, __shfl_xor_sync(0xffffffffu, v, 1));
    v = fminf(v, __shfl_xor_sync(0xffffffffu, v, 2));
    return v;
}

#define COLLECT(rowidx, code) do { \
    int p = atomicAdd(&g_ccnt[rowidx], 1); \
    if (p < MAXC) g_cand[(size_t)(rowidx) * MAXC + p] = (code); \
} while (0)

// ---------------- prep kernels ----------------
__global__ void vq_transpose(const float* __restrict__ embed) {
    __shared__ float t[32][33];
    int k0 = blockIdx.x * 32, d0 = blockIdx.y * 32;
    int tx = threadIdx.x, ty = threadIdx.y;
    #pragma unroll
    for (int j = ty; j < 32; j += 8)
        t[j][tx] = embed[(size_t)(d0 + j) * KQ + k0 + tx];
    __syncthreads();
    #pragma unroll
    for (int j = ty; j < 32; j += 8) {
        float v = t[tx][j];
        g_embedT[(size_t)(k0 + j) * DQ + d0 + tx] = v;
        g_eh[(size_t)(k0 + j) * DQ + d0 + tx]     = __float2half_rn(v);
    }
}

__global__ void vq_esq() {
    int w = threadIdx.x >> 5, lane = threadIdx.x & 31;
    int k = blockIdx.x * 8 + w;
    float s = 0.f;
    #pragma unroll
    for (int j = 0; j < 8; j++) {
        float v = g_embedT[(size_t)k * DQ + j * 32 + lane];
        s = fmaf(v, v, s);
    }
    #pragma unroll
    for (int o = 16; o; o >>= 1) s += __shfl_xor_sync(0xffffffffu, s, o);
    if (lane == 0) g_esq[k] = s;
}

__global__ void vq_x2h(const float* __restrict__ x) {
    int i = blockIdx.x * blockDim.x + threadIdx.x;  // one float4
    float4 v = *(const float4*)&x[(size_t)i * 4];
    __half2* o = (__half2*)&g_xh[(size_t)i * 4];
    o[0] = __floats2half2_rn(v.x, v.y);
    o[1] = __floats2half2_rn(v.z, v.w);
    if (i < NQ) g_ccnt[i] = 0;
}

// ---------------- GEMM: fp16 mma.sync + fused candidate selection ----------------
// CTA: 128 queries x 128 codes per tile, 64 tiles (full K per CTA). 8 warps
// 4M x 2N, warp tile 32x64. Epilogue: stale-threshold single-phase collection
// (two-phase on tile 0 only); quad-shuffle min + 1 atomicMin per quad.
#define GM_BM    128
#define GM_BN    128
#define APITCH   528          // bytes per 256-half row (+16 pad)
#define A_OFF    0            // 128*528 = 67584
#define B_OFF    67584        // 2 x 128*528
#define B_BUF    67584
#define SMIN_OFF 202752       // u32[128] per-row running min keys
#define GM_SMEM  203264

__global__ __launch_bounds__(256, 1)
void vq_gemm() {
    extern __shared__ char smem[];
    u32 sb  = smem_u32(smem);
    u32* smin = (u32*)(smem + SMIN_OFF);
    int tid  = threadIdx.x;
    int wid  = tid >> 5, lane = tid & 31;
    int wm   = wid >> 1;          // 0..3  (M group of 32 rows)
    int wn   = wid & 1;           // 0..1  (N group of 64 cols)
    int qbase = blockIdx.x * GM_BM;

    if (tid < GM_BM) smin[tid] = 0xFFFFFFFFu;

    // prologue: A tile 128x32 chunks (4096) + B buf0 128x32 (4096)
    #pragma unroll
    for (int i = 0; i < 16; i++) {
        int id = tid + i * 256;
        int r = id >> 5, c = id & 31;
        cp16(sb + A_OFF + (u32)r * APITCH + (u32)c * 16,
             &g_xh[(size_t)(qbase + r) * DQ + c * 8]);
    }
    #pragma unroll
    for (int i = 0; i < 16; i++) {
        int id = tid + i * 256;
        int r = id >> 5, c = id & 31;
        cp16(sb + B_OFF + (u32)r * APITCH + (u32)c * 16,
             &g_eh[(size_t)r * DQ + c * 8]);
    }
    cp_commit();

    // per-thread ldmatrix base offsets
    u32 lrow = (u32)(lane & 15);
    u32 lcol = (u32)(lane >> 4) * 16;     // bytes (+8 halfs)
    u32 a_base   = sb + A_OFF + ((u32)wm * 32 + lrow) * APITCH + lcol;
    u32 b_rowoff = ((u32)wn * 64 + lrow) * APITCH + lcol;

    int ep_r0 = wm * 32 + (lane >> 2);            // epilogue row (frag row 0)
    int ep_c0 = wn * 64 + (lane & 3) * 2;         // epilogue col base

    for (int nt = 0; nt < KQ / GM_BN; nt++) {
        cp_wait0();
        __syncthreads();   // buf(nt) ready; ALL warps done with buf((nt+1)&1)

        // issue prefetch of next B AFTER the barrier (write/read ordering)
        if (nt + 1 < KQ / GM_BN) {
            int nb = (nt + 1) * GM_BN;
            u32 bb = sb + B_OFF + (u32)((nt + 1) & 1) * B_BUF;
            #pragma unroll
            for (int i = 0; i < 16; i++) {
                int id = tid + i * 256;
                int r = id >> 5, c = id & 31;
                cp16(bb + (u32)r * APITCH + (u32)c * 16,
                     &g_eh[(size_t)(nb + r) * DQ + c * 8]);
            }
            cp_commit();
        }

        u32 bbase = sb + B_OFF + (u32)(nt & 1) * B_BUF + b_rowoff;

        u32 c[2][8][2];
        #pragma unroll
        for (int mf = 0; mf < 2; mf++)
            #pragma unroll
            for (int nf = 0; nf < 8; nf++) { c[mf][nf][0] = 0u; c[mf][nf][1] = 0u; }

        #pragma unroll
        for (int k = 0; k < DQ / 16; k++) {
            u32 koff = (u32)k * 32;   // 16 halfs = 32 bytes
            u32 a0[4], a1[4], b0[4], b1[4], b2[4], b3[4];
            LDSM_X4(a0, a_base + koff);
            LDSM_X4(a1, a_base + 16 * APITCH + koff);
            LDSM_X4(b0, bbase + koff);
            LDSM_X4(b1, bbase + 16 * APITCH + koff);
            LDSM_X4(b2, bbase + 32 * APITCH + koff);
            LDSM_X4(b3, bbase + 48 * APITCH + koff);
            MMAF16(c[0][0], a0, b0[0], b0[2]);
            MMAF16(c[0][1], a0, b0[1], b0[3]);
            MMAF16(c[0][2], a0, b1[0], b1[2]);
            MMAF16(c[0][3], a0, b1[1], b1[3]);
            MMAF16(c[0][4], a0, b2[0], b2[2]);
            MMAF16(c[0][5], a0, b2[1], b2[3]);
            MMAF16(c[0][6], a0, b3[0], b3[2]);
            MMAF16(c[0][7], a0, b3[1], b3[3]);
            MMAF16(c[1][0], a1, b0[0], b0[2]);
            MMAF16(c[1][1], a1, b0[1], b0[3]);
            MMAF16(c[1][2], a1, b1[0], b1[2]);
            MMAF16(c[1][3], a1, b1[1], b1[3]);
            MMAF16(c[1][4], a1, b2[0], b2[2]);
            MMAF16(c[1][5], a1, b2[1], b2[3]);
            MMAF16(c[1][6], a1, b3[0], b3[2]);
            MMAF16(c[1][7], a1, b3[1], b3[3]);
        }

        // ---- epilogue ----
        float2 eqv[8];
        #pragma unroll
        for (int nf = 0; nf < 8; nf++)
            eqv[nf] = __ldg((const float2*)&g_esq[nt * GM_BN + ep_c0 + nf * 8]);

        if (nt == 0) {
            // two-phase: mins first, then collect with fresh threshold
            float mA[2] = {3.4e38f, 3.4e38f}, mB[2] = {3.4e38f, 3.4e38f};
            #pragma unroll
            for (int mf = 0; mf < 2; mf++)
                #pragma unroll
                for (int nf = 0; nf < 8; nf++) {
                    float2 lo = __half22float2(*(__half2*)&c[mf][nf][0]);
                    float2 hi = __half22float2(*(__half2*)&c[mf][nf][1]);
                    mA[mf] = fminf(mA[mf], fminf(fmaf(-2.f, lo.x, eqv[nf].x),
                                                 fmaf(-2.f, lo.y, eqv[nf].y)));
                    mB[mf] = fminf(mB[mf], fminf(fmaf(-2.f, hi.x, eqv[nf].x),
                                                 fmaf(-2.f, hi.y, eqv[nf].y)));
                }
            #pragma unroll
            for (int mf = 0; mf < 2; mf++) {
                float a = quadmin(mA[mf]), b = quadmin(mB[mf]);
                if ((lane & 3) == 0) {
                    atomicMin(&smin[ep_r0 + mf * 16],     fkey(a));
                    atomicMin(&smin[ep_r0 + mf * 16 + 8], fkey(b));
                }
            }
            __syncthreads();
            #pragma unroll
            for (int mf = 0; mf < 2; mf++) {
                float thrA = funkey(smin[ep_r0 + mf * 16]) + MARGIN;
                float thrB = funkey(smin[ep_r0 + mf * 16 + 8]) + MARGIN;
                int rowA = qbase + ep_r0 + mf * 16, rowB = rowA + 8;
                #pragma unroll
                for (int nf = 0; nf < 8; nf++) {
                    int gc = ep_c0 + nf * 8;
                    float2 lo = __half22float2(*(__half2*)&c[mf][nf][0]);
                    float2 hi = __half22float2(*(__half2*)&c[mf][nf][1]);
                    float d0 = fmaf(-2.f, lo.x, eqv[nf].x);
                    float d1 = fmaf(-2.f, lo.y, eqv[nf].y);
                    float d2 = fmaf(-2.f, hi.x, eqv[nf].x);
                    float d3 = fmaf(-2.f, hi.y, eqv[nf].y);
                    if (d0 <= thrA) COLLECT(rowA, gc);
                    if (d1 <= thrA) COLLECT(rowA, gc + 1);
                    if (d2 <= thrB) COLLECT(rowB, gc);
                    if (d3 <= thrB) COLLECT(rowB, gc + 1);
                }
            }
        } else {
            // single-phase: stale threshold (>= final min, superset-safe)
            float thrA[2], thrB[2];
            int rowA[2], rowB[2];
            #pragma unroll
            for (int mf = 0; mf < 2; mf++) {
                thrA[mf] = funkey(smin[ep_r0 + mf * 16]) + MARGIN;
                thrB[mf] = funkey(smin[ep_r0 + mf * 16 + 8]) + MARGIN;
                rowA[mf] = qbase + ep_r0 + mf * 16;
                rowB[mf] = rowA[mf] + 8;
            }
            float mA[2] = {3.4e38f, 3.4e38f}, mB[2] = {3.4e38f, 3.4e38f};
            #pragma unroll
            for (int mf = 0; mf < 2; mf++)
                #pragma unroll
                for (int nf = 0; nf < 8; nf++) {
                    int gc = nt * GM_BN + ep_c0 + nf * 8;
                    float2 lo = __half22float2(*(__half2*)&c[mf][nf][0]);
                    float2 hi = __half22float2(*(__half2*)&c[mf][nf][1]);
                    float d0 = fmaf(-2.f, lo.x, eqv[nf].x);
                    float d1 = fmaf(-2.f, lo.y, eqv[nf].y);
                    float d2 = fmaf(-2.f, hi.x, eqv[nf].x);
                    float d3 = fmaf(-2.f, hi.y, eqv[nf].y);
                    mA[mf] = fminf(mA[mf], fminf(d0, d1));
                    mB[mf] = fminf(mB[mf], fminf(d2, d3));
                    if (d0 <= thrA[mf]) COLLECT(rowA[mf], gc);
                    if (d1 <= thrA[mf]) COLLECT(rowA[mf], gc + 1);
                    if (d2 <= thrB[mf]) COLLECT(rowB[mf], gc);
                    if (d3 <= thrB[mf]) COLLECT(rowB[mf], gc + 1);
                }
            #pragma unroll
            for (int mf = 0; mf < 2; mf++) {
                float a = quadmin(mA[mf]), b = quadmin(mB[mf]);
                if ((lane & 3) == 0) {
                    atomicMin(&smin[ep_r0 + mf * 16],     fkey(a));
                    atomicMin(&smin[ep_r0 + mf * 16 + 8], fkey(b));
                }
            }
        }
    }
}

// ---------------- rescore: exact fp32 over candidate list ----------------
__global__ __launch_bounds__(256, 4)
void vq_rescore2(const float* __restrict__ x, float* __restrict__ out) {
    __shared__ float xrow[DQ];
    __shared__ float cd[MAXC];
    __shared__ int   sbk;

    int row = blockIdx.x;
    int tid = threadIdx.x;
    int wid = tid >> 5, lane = tid & 31;

    xrow[tid] = x[(size_t)row * DQ + tid];
    int cnt = g_ccnt[row];
    if (cnt > MAXC) cnt = MAXC;
    __syncthreads();

    // warp-parallel exact fp32 rescore of candidates
    for (int j = wid; j < cnt; j += 8) {
        int k = g_cand[(size_t)row * MAXC + j];
        float p = 0.f;
        #pragma unroll
        for (int i = 0; i < 8; i++)
            p = fmaf(xrow[i * 32 + lane], g_embedT[(size_t)k * DQ + i * 32 + lane], p);
        #pragma unroll
        for (int o = 16; o; o >>= 1) p += __shfl_xor_sync(0xffffffffu, p, o);
        if (lane == 0) cd[j] = fmaf(-2.f, p, g_esq[k]);
    }
    __syncthreads();

    if (tid == 0) {
        float bv = 3.4e38f; int bk = 0x7fffffff;
        for (int j = 0; j < cnt; j++) {
            int k = g_cand[(size_t)row * MAXC + j];
            float v = cd[j];
            if (v < bv || (v == bv && k < bk)) { bv = v; bk = k; }
        }
        sbk = (cnt > 0) ? bk : 0;
    }
    __syncthreads();

    int bk = sbk;
    if (bk < 0 || bk >= KQ) bk = 0;   // safety net
    out[(size_t)row * DQ + tid] = g_embedT[(size_t)bk * DQ + tid];
}

// ---------------- launch ----------------
extern "C" void kernel_launch(void* const* d_in, const int* in_sizes, int n_in,
                              void* d_out, int out_size) {
    const float* x     = (const float*)d_in[0];
    const float* embed = (const float*)d_in[1];
    float*       out   = (float*)d_out;

    vq_transpose<<<dim3(KQ / 32, DQ / 32), dim3(32, 8)>>>(embed);
    vq_esq<<<KQ / 8, 256>>>();
    vq_x2h<<<(NQ * DQ / 4) / 256, 256>>>(x);

    cudaFuncSetAttribute(vq_gemm, cudaFuncAttributeMaxDynamicSharedMemorySize, GM_SMEM);
    vq_gemm<<<NQ / GM_BM, 256, GM_SMEM>>>();

    vq_rescore2<<<NQ, 256>>>(x, out);
}

// round 14
// speedup vs baseline: 1.5492x; 1.5492x over previous
#include <cuda_runtime.h>
#include <cuda_fp16.h>
#include <cstdint>

#define DQ 256
#define KQ 8192
#define NQ 32768
#define MAXC 64
#define MARGIN 2.5f

typedef unsigned int u32;

// ---------------- device scratch ----------------
__device__ float   g_embedT[KQ * DQ];      // fp32 [K][D]
__device__ __half  g_eh[KQ * DQ];          // fp16 [K][D]
__device__ __half  g_xh[NQ * DQ];          // fp16 [N][D]
__device__ float   g_esq[KQ];
__device__ int     g_cand[(size_t)NQ * MAXC];  // candidate code indices per row
__device__ int     g_ccnt[NQ];                 // candidate counts

// ---------------- helpers ----------------
__device__ __forceinline__ u32 smem_u32(const void* p) {
    u32 a;
    asm("{ .reg .u64 t; cvta.to.shared.u64 t, %1; cvt.u32.u64 %0, t; }" : "=r"(a) : "l"(p));
    return a;
}
__device__ __forceinline__ void cp16(u32 saddr, const void* g) {
    asm volatile("cp.async.cg.shared.global [%0], [%1], 16;" :: "r"(saddr), "l"(g));
}
__device__ __forceinline__ void cp_commit() { asm volatile("cp.async.commit_group;"); }
__device__ __forceinline__ void cp_wait1()  { asm volatile("cp.async.wait_group 1;" ::: "memory"); }
__device__ __forceinline__ void cp_wait0()  { asm volatile("cp.async.wait_group 0;" ::: "memory"); }

#define LDSM_X4(r, addr) \
    asm volatile("ldmatrix.sync.aligned.m8n8.x4.shared.b16 {%0,%1,%2,%3}, [%4];" \
                 : "=r"((r)[0]), "=r"((r)[1]), "=r"((r)[2]), "=r"((r)[3]) : "r"(addr))

// fp16-accumulate HMMA: C/D are 2 regs (half2 x2)
#define MMAF16(c, a, b0, b1) \
    asm volatile("mma.sync.aligned.m16n8k16.row.col.f16.f16.f16.f16 " \
                 "{%0,%1}, {%2,%3,%4,%5}, {%6,%7}, {%0,%1};" \
                 : "+r"((c)[0]), "+r"((c)[1]) \
                 : "r"((a)[0]), "r"((a)[1]), "r"((a)[2]), "r"((a)[3]), "r"(b0), "r"(b1))

// order-preserving float <-> u32 key (for atomicMin)
__device__ __forceinline__ u32 fkey(float f) {
    u32 b = __float_as_uint(f);
    return (b & 0x80000000u) ? ~b : (b | 0x80000000u);
}
__device__ __forceinline__ float funkey(u32 k) {
    u32 b = (k & 0x80000000u) ? (k & 0x7FFFFFFFu) : ~k;
    return __uint_as_float(b);
}
__device__ __forceinline__ float quadmin(float v) {
    v = fminf(v, __shfl_xor_sync(0xffffffffu, v, 1));
    v = fminf(v, __shfl_xor_sync(0xffffffffu, v, 2));
    return v;
}

#define COLLECT(rowidx, code) do { \
    int p = atomicAdd(&g_ccnt[rowidx], 1); \
    if (p < MAXC) g_cand[(size_t)(rowidx) * MAXC + p] = (code); \
} while (0)

// ---------------- prep kernels ----------------
__global__ void vq_transpose(const float* __restrict__ embed) {
    __shared__ float t[32][33];
    int k0 = blockIdx.x * 32, d0 = blockIdx.y * 32;
    int tx = threadIdx.x, ty = threadIdx.y;
    #pragma unroll
    for (int j = ty; j < 32; j += 8)
        t[j][tx] = embed[(size_t)(d0 + j) * KQ + k0 + tx];
    __syncthreads();
    #pragma unroll
    for (int j = ty; j < 32; j += 8) {
        float v = t[tx][j];
        g_embedT[(size_t)(k0 + j) * DQ + d0 + tx] = v;
        g_eh[(size_t)(k0 + j) * DQ + d0 + tx]     = __float2half_rn(v);
    }
}

__global__ void vq_esq() {
    int w = threadIdx.x >> 5, lane = threadIdx.x & 31;
    int k = blockIdx.x * 8 + w;
    float s = 0.f;
    #pragma unroll
    for (int j = 0; j < 8; j++) {
        float v = g_embedT[(size_t)k * DQ + j * 32 + lane];
        s = fmaf(v, v, s);
    }
    #pragma unroll
    for (int o = 16; o; o >>= 1) s += __shfl_xor_sync(0xffffffffu, s, o);
    if (lane == 0) g_esq[k] = s;
}

__global__ void vq_x2h(const float* __restrict__ x) {
    int i = blockIdx.x * blockDim.x + threadIdx.x;  // one float4
    float4 v = *(const float4*)&x[(size_t)i * 4];
    __half2* o = (__half2*)&g_xh[(size_t)i * 4];
    o[0] = __floats2half2_rn(v.x, v.y);
    o[1] = __floats2half2_rn(v.z, v.w);
    if (i < NQ) g_ccnt[i] = 0;
}

// ---------------- GEMM: fp16 mma.sync + fused candidate selection ----------------
// Identical to R12 except phase A: quad-shuffle min fold, then one atomicMin
// per quad leader (1024 -> 256 atomics/tile, 8-way -> 2-way contention).
#define GM_BM    128
#define GM_BN    128
#define APITCH   528          // bytes per 256-half row (+16 pad)
#define A_OFF    0            // 128*528 = 67584
#define B_OFF    67584        // 2 x 128*528
#define B_BUF    67584
#define SMIN_OFF 202752       // u32[128] per-row running min keys
#define GM_SMEM  203264

__global__ __launch_bounds__(256, 1)
void vq_gemm() {
    extern __shared__ char smem[];
    u32 sb  = smem_u32(smem);
    u32* smin = (u32*)(smem + SMIN_OFF);
    int tid  = threadIdx.x;
    int wid  = tid >> 5, lane = tid & 31;
    int wm   = wid >> 1;          // 0..3  (M group of 32 rows)
    int wn   = wid & 1;           // 0..1  (N group of 64 cols)
    int qbase = blockIdx.x * GM_BM;

    if (tid < GM_BM) smin[tid] = 0xFFFFFFFFu;

    // prologue: A tile 128x32 chunks (4096) + B buf0 128x32 (4096)
    #pragma unroll
    for (int i = 0; i < 16; i++) {
        int id = tid + i * 256;
        int r = id >> 5, c = id & 31;
        cp16(sb + A_OFF + (u32)r * APITCH + (u32)c * 16,
             &g_xh[(size_t)(qbase + r) * DQ + c * 8]);
    }
    #pragma unroll
    for (int i = 0; i < 16; i++) {
        int id = tid + i * 256;
        int r = id >> 5, c = id & 31;
        cp16(sb + B_OFF + (u32)r * APITCH + (u32)c * 16,
             &g_eh[(size_t)r * DQ + c * 8]);
    }
    cp_commit();

    // per-thread ldmatrix base offsets
    u32 lrow = (u32)(lane & 15);
    u32 lcol = (u32)(lane >> 4) * 16;     // bytes (+8 halfs)
    u32 a_base   = sb + A_OFF + ((u32)wm * 32 + lrow) * APITCH + lcol;
    u32 b_rowoff = ((u32)wn * 64 + lrow) * APITCH + lcol;

    int ep_r0 = wm * 32 + (lane >> 2);            // epilogue row (frag row 0)
    int ep_c0 = wn * 64 + (lane & 3) * 2;         // epilogue col base

    for (int nt = 0; nt < KQ / GM_BN; nt++) {
        // prefetch next B into the other buffer
        if (nt + 1 < KQ / GM_BN) {
            int nb = (nt + 1) * GM_BN;
            u32 bb = sb + B_OFF + (u32)((nt + 1) & 1) * B_BUF;
            #pragma unroll
            for (int i = 0; i < 16; i++) {
                int id = tid + i * 256;
                int r = id >> 5, c = id & 31;
                cp16(bb + (u32)r * APITCH + (u32)c * 16,
                     &g_eh[(size_t)(nb + r) * DQ + c * 8]);
            }
            cp_commit();
            cp_wait1();
        } else {
            cp_wait0();
        }
        __syncthreads();   // also separates prev tile's phase B from this phase A

        u32 bbase = sb + B_OFF + (u32)(nt & 1) * B_BUF + b_rowoff;

        u32 c[2][8][2];
        #pragma unroll
        for (int mf = 0; mf < 2; mf++)
            #pragma unroll
            for (int nf = 0; nf < 8; nf++) { c[mf][nf][0] = 0u; c[mf][nf][1] = 0u; }

        #pragma unroll
        for (int k = 0; k < DQ / 16; k++) {
            u32 koff = (u32)k * 32;   // 16 halfs = 32 bytes
            u32 a0[4], a1[4], b0[4], b1[4], b2[4], b3[4];
            LDSM_X4(a0, a_base + koff);
            LDSM_X4(a1, a_base + 16 * APITCH + koff);
            LDSM_X4(b0, bbase + koff);
            LDSM_X4(b1, bbase + 16 * APITCH + koff);
            LDSM_X4(b2, bbase + 32 * APITCH + koff);
            LDSM_X4(b3, bbase + 48 * APITCH + koff);
            MMAF16(c[0][0], a0, b0[0], b0[2]);
            MMAF16(c[0][1], a0, b0[1], b0[3]);
            MMAF16(c[0][2], a0, b1[0], b1[2]);
            MMAF16(c[0][3], a0, b1[1], b1[3]);
            MMAF16(c[0][4], a0, b2[0], b2[2]);
            MMAF16(c[0][5], a0, b2[1], b2[3]);
            MMAF16(c[0][6], a0, b3[0], b3[2]);
            MMAF16(c[0][7], a0, b3[1], b3[3]);
            MMAF16(c[1][0], a1, b0[0], b0[2]);
            MMAF16(c[1][1], a1, b0[1], b0[3]);
            MMAF16(c[1][2], a1, b1[0], b1[2]);
            MMAF16(c[1][3], a1, b1[1], b1[3]);
            MMAF16(c[1][4], a1, b2[0], b2[2]);
            MMAF16(c[1][5], a1, b2[1], b2[3]);
            MMAF16(c[1][6], a1, b3[0], b3[2]);
            MMAF16(c[1][7], a1, b3[1], b3[3]);
        }

        // epilogue, phase A: per-row local mins -> quad fold -> one atomic/quad
        float2 eqv[8];
        #pragma unroll
        for (int nf = 0; nf < 8; nf++)
            eqv[nf] = __ldg((const float2*)&g_esq[nt * GM_BN + ep_c0 + nf * 8]);

        float mA[2] = {3.4e38f, 3.4e38f};   // rows ep_r0 + mf*16
        float mB[2] = {3.4e38f, 3.4e38f};   // rows ep_r0 + mf*16 + 8
        #pragma unroll
        for (int mf = 0; mf < 2; mf++)
            #pragma unroll
            for (int nf = 0; nf < 8; nf++) {
                float2 lo = __half22float2(*(__half2*)&c[mf][nf][0]);
                float2 hi = __half22float2(*(__half2*)&c[mf][nf][1]);
                float d0 = fmaf(-2.f, lo.x, eqv[nf].x);
                float d1 = fmaf(-2.f, lo.y, eqv[nf].y);
                float d2 = fmaf(-2.f, hi.x, eqv[nf].x);
                float d3 = fmaf(-2.f, hi.y, eqv[nf].y);
                mA[mf] = fminf(mA[mf], fminf(d0, d1));
                mB[mf] = fminf(mB[mf], fminf(d2, d3));
            }
        #pragma unroll
        for (int mf = 0; mf < 2; mf++) {
            float a = quadmin(mA[mf]);
            float b = quadmin(mB[mf]);
            if ((lane & 3) == 0) {
                atomicMin(&smin[ep_r0 + mf * 16],     fkey(a));
                atomicMin(&smin[ep_r0 + mf * 16 + 8], fkey(b));
            }
        }
        __syncthreads();   // publish mins; also releases B buffer for reuse

        // phase B: collect candidates (dist <= rowmin + MARGIN)
        #pragma unroll
        for (int mf = 0; mf < 2; mf++) {
            float thrA = funkey(smin[ep_r0 + mf * 16]) + MARGIN;
            float thrB = funkey(smin[ep_r0 + mf * 16 + 8]) + MARGIN;
            int rowA = qbase + ep_r0 + mf * 16;
            int rowB = rowA + 8;
            #pragma unroll
            for (int nf = 0; nf < 8; nf++) {
                int gc = nt * GM_BN + ep_c0 + nf * 8;
                float2 lo = __half22float2(*(__half2*)&c[mf][nf][0]);
                float2 hi = __half22float2(*(__half2*)&c[mf][nf][1]);
                float d0 = fmaf(-2.f, lo.x, eqv[nf].x);
                float d1 = fmaf(-2.f, lo.y, eqv[nf].y);
                float d2 = fmaf(-2.f, hi.x, eqv[nf].x);
                float d3 = fmaf(-2.f, hi.y, eqv[nf].y);
                if (d0 <= thrA) COLLECT(rowA, gc);
                if (d1 <= thrA) COLLECT(rowA, gc + 1);
                if (d2 <= thrB) COLLECT(rowB, gc);
                if (d3 <= thrB) COLLECT(rowB, gc + 1);
            }
        }
    }
}

// ---------------- rescore: exact fp32 over candidate list ----------------
__global__ __launch_bounds__(256, 4)
void vq_rescore2(const float* __restrict__ x, float* __restrict__ out) {
    __shared__ float xrow[DQ];
    __shared__ float cd[MAXC];
    __shared__ int   sbk;

    int row = blockIdx.x;
    int tid = threadIdx.x;
    int wid = tid >> 5, lane = tid & 31;

    xrow[tid] = x[(size_t)row * DQ + tid];
    int cnt = g_ccnt[row];
    if (cnt > MAXC) cnt = MAXC;
    __syncthreads();

    // warp-parallel exact fp32 rescore of candidates
    for (int j = wid; j < cnt; j += 8) {
        int k = g_cand[(size_t)row * MAXC + j];
        float p = 0.f;
        #pragma unroll
        for (int i = 0; i < 8; i++)
            p = fmaf(xrow[i * 32 + lane], g_embedT[(size_t)k * DQ + i * 32 + lane], p);
        #pragma unroll
        for (int o = 16; o; o >>= 1) p += __shfl_xor_sync(0xffffffffu, p, o);
        if (lane == 0) cd[j] = fmaf(-2.f, p, g_esq[k]);
    }
    __syncthreads();

    if (tid == 0) {
        float bv = 3.4e38f; int bk = 0x7fffffff;
        for (int j = 0; j < cnt; j++) {
            int k = g_cand[(size_t)row * MAXC + j];
            float v = cd[j];
            if (v < bv || (v == bv && k < bk)) { bv = v; bk = k; }
        }
        sbk = (cnt > 0) ? bk : 0;
    }
    __syncthreads();

    int bk = sbk;
    if (bk < 0 || bk >= KQ) bk = 0;   // safety net
    out[(size_t)row * DQ + tid] = g_embedT[(size_t)bk * DQ + tid];
}

// ---------------- launch ----------------
extern "C" void kernel_launch(void* const* d_in, const int* in_sizes, int n_in,
                              void* d_out, int out_size) {
    const float* x     = (const float*)d_in[0];
    const float* embed = (const float*)d_in[1];
    float*       out   = (float*)d_out;

    vq_transpose<<<dim3(KQ / 32, DQ / 32), dim3(32, 8)>>>(embed);
    vq_esq<<<KQ / 8, 256>>>();
    vq_x2h<<<(NQ * DQ / 4) / 256, 256>>>(x);

    cudaFuncSetAttribute(vq_gemm, cudaFuncAttributeMaxDynamicSharedMemorySize, GM_SMEM);
    vq_gemm<<<NQ / GM_BM, 256, GM_SMEM>>>();

    vq_rescore2<<<NQ, 256>>>(x, out);
}

// round 16
// speedup vs baseline: 1.9393x; 1.2518x over previous
#include <cuda_runtime.h>
#include <cuda_fp16.h>
#include <cstdint>

#define DQ 256
#define KQ 8192
#define NQ 32768
#define KSPLIT 4

typedef unsigned int u32;

// ---------------- device scratch ----------------
__device__ float   g_embedT[KQ * DQ];      // fp32 [K][D]
__device__ __half  g_eh[KQ * DQ];          // fp16 [K][D]
__device__ __half  g_xh[NQ * DQ];          // fp16 [N][D]
__device__ float   g_esq[KQ];
__device__ __half  g_S[(size_t)NQ * KQ];   // fp16 (dist-256), 512MB

// ---------------- helpers ----------------
__device__ __forceinline__ u32 smem_u32(const void* p) {
    u32 a;
    asm("{ .reg .u64 t; cvta.to.shared.u64 t, %1; cvt.u32.u64 %0, t; }" : "=r"(a) : "l"(p));
    return a;
}
__device__ __forceinline__ void cp16(u32 saddr, const void* g) {
    asm volatile("cp.async.cg.shared.global [%0], [%1], 16;" :: "r"(saddr), "l"(g));
}
__device__ __forceinline__ void cp_commit() { asm volatile("cp.async.commit_group;"); }
__device__ __forceinline__ void cp_wait1()  { asm volatile("cp.async.wait_group 1;" ::: "memory"); }
__device__ __forceinline__ void cp_wait0()  { asm volatile("cp.async.wait_group 0;" ::: "memory"); }

#define LDSM_X4(r, addr) \
    asm volatile("ldmatrix.sync.aligned.m8n8.x4.shared.b16 {%0,%1,%2,%3}, [%4];" \
                 : "=r"((r)[0]), "=r"((r)[1]), "=r"((r)[2]), "=r"((r)[3]) : "r"(addr))

// fp16-accumulate HMMA: C/D are 2 regs (half2 x2)
#define MMAF16(c, a, b0, b1) \
    asm volatile("mma.sync.aligned.m16n8k16.row.col.f16.f16.f16.f16 " \
                 "{%0,%1}, {%2,%3,%4,%5}, {%6,%7}, {%0,%1};" \
                 : "+r"((c)[0]), "+r"((c)[1]) \
                 : "r"((a)[0]), "r"((a)[1]), "r"((a)[2]), "r"((a)[3]), "r"(b0), "r"(b1))

// ---------------- prep kernels ----------------
__global__ void vq_transpose(const float* __restrict__ embed) {
    __shared__ float t[32][33];
    int k0 = blockIdx.x * 32, d0 = blockIdx.y * 32;
    int tx = threadIdx.x, ty = threadIdx.y;
    #pragma unroll
    for (int j = ty; j < 32; j += 8)
        t[j][tx] = embed[(size_t)(d0 + j) * KQ + k0 + tx];
    __syncthreads();
    #pragma unroll
    for (int j = ty; j < 32; j += 8) {
        float v = t[tx][j];
        g_embedT[(size_t)(k0 + j) * DQ + d0 + tx] = v;
        g_eh[(size_t)(k0 + j) * DQ + d0 + tx]     = __float2half_rn(v);
    }
}

__global__ void vq_esq() {
    int w = threadIdx.x >> 5, lane = threadIdx.x & 31;
    int k = blockIdx.x * 8 + w;
    float s = 0.f;
    #pragma unroll
    for (int j = 0; j < 8; j++) {
        float v = g_embedT[(size_t)k * DQ + j * 32 + lane];
        s = fmaf(v, v, s);
    }
    #pragma unroll
    for (int o = 16; o; o >>= 1) s += __shfl_xor_sync(0xffffffffu, s, o);
    if (lane == 0) g_esq[k] = s;
}

__global__ void vq_x2h(const float* __restrict__ x) {
    int i = blockIdx.x * blockDim.x + threadIdx.x;  // one float4
    float4 v = *(const float4*)&x[(size_t)i * 4];
    __half2* o = (__half2*)&g_xh[(size_t)i * 4];
    o[0] = __floats2half2_rn(v.x, v.y);
    o[1] = __floats2half2_rn(v.z, v.w);
}

// ---------------- GEMM: fp16 mma.sync (fp16 accum), dist-256 -> fp16 S ----------------
// grid (256, 4): blockIdx.x = M-tile (128 queries), blockIdx.y = K quarter
// (16 of 64 code-tiles). 1024 CTAs -> 7 waves, 1.2% tail (vs 13.5% at 256).
#define GM_BM    128
#define GM_BN    128
#define APITCH   528          // bytes per 256-half row (+16 pad)
#define A_OFF    0            // 128*528 = 67584
#define B_OFF    67584        // 2 x 128*528
#define B_BUF    67584
#define ST_PITCH 272          // stage: 128 rows x 128 halfs (+16B pad), in B buf
#define GM_SMEM  202752
#define NT_PER   (KQ / GM_BN / KSPLIT)   // 16

__global__ __launch_bounds__(256, 1)
void vq_gemm() {
    extern __shared__ char smem[];
    u32 sb  = smem_u32(smem);
    int tid  = threadIdx.x;
    int wid  = tid >> 5, lane = tid & 31;
    int wm   = wid >> 1;          // 0..3  (M group of 32 rows)
    int wn   = wid & 1;           // 0..1  (N group of 64 cols)
    int qbase = blockIdx.x * GM_BM;
    int nt0   = blockIdx.y * NT_PER;

    // prologue: A tile 128x32 chunks (4096) + B buf0 128x32 (4096)
    #pragma unroll
    for (int i = 0; i < 16; i++) {
        int id = tid + i * 256;
        int r = id >> 5, c = id & 31;
        cp16(sb + A_OFF + (u32)r * APITCH + (u32)c * 16,
             &g_xh[(size_t)(qbase + r) * DQ + c * 8]);
    }
    #pragma unroll
    for (int i = 0; i < 16; i++) {
        int id = tid + i * 256;
        int r = id >> 5, c = id & 31;
        cp16(sb + B_OFF + (u32)r * APITCH + (u32)c * 16,
             &g_eh[(size_t)(nt0 * GM_BN + r) * DQ + c * 8]);
    }
    cp_commit();

    // per-thread ldmatrix base offsets
    u32 lrow = (u32)(lane & 15);
    u32 lcol = (u32)(lane >> 4) * 16;     // bytes (+8 halfs)
    u32 a_base   = sb + A_OFF + ((u32)wm * 32 + lrow) * APITCH + lcol;
    u32 b_rowoff = ((u32)wn * 64 + lrow) * APITCH + lcol;

    int ep_r0 = wm * 32 + (lane >> 2);            // epilogue row (frag row 0)
    int ep_c0 = wn * 64 + (lane & 3) * 2;         // epilogue col base

    for (int ntl = 0; ntl < NT_PER; ntl++) {
        int nt = nt0 + ntl;
        u32 buf = sb + B_OFF + (u32)(ntl & 1) * B_BUF;

        // prefetch next B into the other buffer
        if (ntl + 1 < NT_PER) {
            int nb = (nt + 1) * GM_BN;
            u32 bb = sb + B_OFF + (u32)((ntl + 1) & 1) * B_BUF;
            #pragma unroll
            for (int i = 0; i < 16; i++) {
                int id = tid + i * 256;
                int r = id >> 5, c = id & 31;
                cp16(bb + (u32)r * APITCH + (u32)c * 16,
                     &g_eh[(size_t)(nb + r) * DQ + c * 8]);
            }
            cp_commit();
            cp_wait1();
        } else {
            cp_wait0();
        }
        __syncthreads();

        u32 bbase = buf + b_rowoff;

        u32 c[2][8][2];
        #pragma unroll
        for (int mf = 0; mf < 2; mf++)
            #pragma unroll
            for (int nf = 0; nf < 8; nf++) { c[mf][nf][0] = 0u; c[mf][nf][1] = 0u; }

        #pragma unroll
        for (int k = 0; k < DQ / 16; k++) {
            u32 koff = (u32)k * 32;   // 16 halfs = 32 bytes
            u32 a0[4], a1[4], b0[4], b1[4], b2[4], b3[4];
            LDSM_X4(a0, a_base + koff);
            LDSM_X4(a1, a_base + 16 * APITCH + koff);
            LDSM_X4(b0, bbase + koff);
            LDSM_X4(b1, bbase + 16 * APITCH + koff);
            LDSM_X4(b2, bbase + 32 * APITCH + koff);
            LDSM_X4(b3, bbase + 48 * APITCH + koff);
            MMAF16(c[0][0], a0, b0[0], b0[2]);
            MMAF16(c[0][1], a0, b0[1], b0[3]);
            MMAF16(c[0][2], a0, b1[0], b1[2]);
            MMAF16(c[0][3], a0, b1[1], b1[3]);
            MMAF16(c[0][4], a0, b2[0], b2[2]);
            MMAF16(c[0][5], a0, b2[1], b2[3]);
            MMAF16(c[0][6], a0, b3[0], b3[2]);
            MMAF16(c[0][7], a0, b3[1], b3[3]);
            MMAF16(c[1][0], a1, b0[0], b0[2]);
            MMAF16(c[1][1], a1, b0[1], b0[3]);
            MMAF16(c[1][2], a1, b1[0], b1[2]);
            MMAF16(c[1][3], a1, b1[1], b1[3]);
            MMAF16(c[1][4], a1, b2[0], b2[2]);
            MMAF16(c[1][5], a1, b2[1], b2[3]);
            MMAF16(c[1][6], a1, b3[0], b3[2]);
            MMAF16(c[1][7], a1, b3[1], b3[3]);
        }
        __syncthreads();   // all warps done reading this B buffer

        // epilogue: dist-256 -> fp16, stage into the dead B buffer
        float2 eqv[8];
        #pragma unroll
        for (int nf = 0; nf < 8; nf++)
            eqv[nf] = __ldg((const float2*)&g_esq[nt * GM_BN + ep_c0 + nf * 8]);
        #pragma unroll
        for (int mf = 0; mf < 2; mf++) {
            int r0 = ep_r0 + mf * 16;
            #pragma unroll
            for (int nf = 0; nf < 8; nf++) {
                int col = ep_c0 + nf * 8;
                float2 lo = __half22float2(*(__half2*)&c[mf][nf][0]);
                float2 hi = __half22float2(*(__half2*)&c[mf][nf][1]);
                float d0 = fmaf(-2.f, lo.x, eqv[nf].x) - 256.f;
                float d1 = fmaf(-2.f, lo.y, eqv[nf].y) - 256.f;
                float d2 = fmaf(-2.f, hi.x, eqv[nf].x) - 256.f;
                float d3 = fmaf(-2.f, hi.y, eqv[nf].y) - 256.f;
                __half2 h01 = __floats2half2_rn(d0, d1);
                __half2 h23 = __floats2half2_rn(d2, d3);
                u32 sa0 = buf + (u32)r0 * ST_PITCH + (u32)col * 2;
                u32 sa1 = sa0 + 8 * ST_PITCH;
                asm volatile("st.shared.b32 [%0], %1;" :: "r"(sa0), "r"(*(u32*)&h01) : "memory");
                asm volatile("st.shared.b32 [%0], %1;" :: "r"(sa1), "r"(*(u32*)&h23) : "memory");
            }
        }
        __syncthreads();

        // coalesced 16B stores to g_S: 128 rows x 16 chunks = 2048
        #pragma unroll
        for (int i = 0; i < 8; i++) {
            int id = tid + i * 256;
            int r = id >> 4, c16 = id & 15;
            u32 sa = buf + (u32)r * ST_PITCH + (u32)c16 * 16;
            u32 v0, v1, v2, v3;
            asm volatile("ld.shared.v4.b32 {%0,%1,%2,%3}, [%4];"
                         : "=r"(v0), "=r"(v1), "=r"(v2), "=r"(v3) : "r"(sa));
            *(uint4*)&g_S[(size_t)(qbase + r) * KQ + nt * GM_BN + c16 * 8] =
                make_uint4(v0, v1, v2, v3);
        }
        __syncthreads();   // stage fully read before next prefetch reuses buf
    }
}

// ---------------- rescore: hmin2 scan + chunk-skip collect + fp32 rescore ----------------
#define MARGIN 2.5f
#define MAXC   64

__global__ __launch_bounds__(256, 4)
void vq_rescore(const float* __restrict__ x, float* __restrict__ out) {
    __shared__ float xrow[DQ];
    __shared__ float red[8];
    __shared__ int   cand[MAXC];
    __shared__ int   s_cnt;
    __shared__ int   s_bestk;
    __shared__ float s_bestv;

    int row = blockIdx.x;
    int tid = threadIdx.x;
    int wid = tid >> 5, lane = tid & 31;

    xrow[tid] = x[(size_t)row * DQ + tid];
    if (tid == 0) { s_cnt = 0; s_bestv = 3.4e38f; s_bestk = 0x7fffffff; }

    // pass 1: hmin2 tree per uint4 (8 halfs -> 1); cache per-chunk mins
    uint4 v[4];
    float m4[4];
    const uint4* Sp = (const uint4*)&g_S[(size_t)row * KQ];
    float mn = 3.4e38f;
    #pragma unroll
    for (int i = 0; i < 4; i++) {
        v[i] = Sp[tid + i * 256];
        __half2 a = __hmin2(*(__half2*)&v[i].x, *(__half2*)&v[i].y);
        __half2 b = __hmin2(*(__half2*)&v[i].z, *(__half2*)&v[i].w);
        __half2 m = __hmin2(a, b);
        float f = __half2float(__hmin(__low2half(m), __high2half(m)));
        m4[i] = f;
        mn = fminf(mn, f);
    }
    #pragma unroll
    for (int o = 16; o; o >>= 1) mn = fminf(mn, __shfl_xor_sync(0xffffffffu, mn, o));
    if (lane == 0) red[wid] = mn;
    __syncthreads();
    if (tid == 0) {
        float m = red[0];
        #pragma unroll
        for (int w = 1; w < 8; w++) m = fminf(m, red[w]);
        red[0] = m;
    }
    __syncthreads();
    float thr = red[0] + MARGIN;

    // pass 2: only chunks whose cached min passes the threshold
    #pragma unroll
    for (int i = 0; i < 4; i++) {
        if (m4[i] <= thr) {
            const __half* h = (const __half*)&v[i];
            #pragma unroll
            for (int j = 0; j < 8; j++) {
                if (__half2float(h[j]) <= thr) {
                    int p = atomicAdd(&s_cnt, 1);
                    if (p < MAXC) cand[p] = (tid + i * 256) * 8 + j;
                }
            }
        }
    }
    __syncthreads();

    int cnt = s_cnt; if (cnt > MAXC) cnt = MAXC;

    for (int j = 0; j < cnt; j++) {
        int k = cand[j];
        float p = xrow[tid] * g_embedT[(size_t)k * DQ + tid];
        #pragma unroll
        for (int o = 16; o; o >>= 1) p += __shfl_xor_sync(0xffffffffu, p, o);
        if (lane == 0) red[wid] = p;
        __syncthreads();
        if (tid == 0) {
            float dot = red[0];
            #pragma unroll
            for (int w = 1; w < 8; w++) dot += red[w];
            float dist = fmaf(-2.f, dot, g_esq[k]);
            if (dist < s_bestv || (dist == s_bestv && k < s_bestk)) {
                s_bestv = dist; s_bestk = k;
            }
        }
        __syncthreads();
    }

    int bk = s_bestk;
    if (bk < 0 || bk >= KQ) bk = 0;   // safety net
    out[(size_t)row * DQ + tid] = g_embedT[(size_t)bk * DQ + tid];
}

// ---------------- launch ----------------
extern "C" void kernel_launch(void* const* d_in, const int* in_sizes, int n_in,
                              void* d_out, int out_size) {
    const float* x     = (const float*)d_in[0];
    const float* embed = (const float*)d_in[1];
    float*       out   = (float*)d_out;

    vq_transpose<<<dim3(KQ / 32, DQ / 32), dim3(32, 8)>>>(embed);
    vq_esq<<<KQ / 8, 256>>>();
    vq_x2h<<<(NQ * DQ / 4) / 256, 256>>>(x);

    cudaFuncSetAttribute(vq_gemm, cudaFuncAttributeMaxDynamicSharedMemorySize, GM_SMEM);
    vq_gemm<<<dim3(NQ / GM_BM, KSPLIT), 256, GM_SMEM>>>();

    vq_rescore<<<NQ, 256>>>(x, out);
}